// round 1
// baseline (speedup 1.0000x reference)
#include <cuda_runtime.h>
#include <math.h>

#define NROWS 65536
#define D 256
#define K 1024
#define QSIZE (NROWS*D)

// scratch (no cudaMalloc allowed)
__device__ float g_eT[K*D];     // embeddings transposed [K][D]
__device__ float g_en2[K];      // ||e_k||^2
__device__ float g_zn2[NROWS];  // ||z_n||^2
__device__ int   g_idx[NROWS];  // argmin indices
__device__ float g_part[8192];  // loss partials
__device__ int   g_hist[K];     // codebook usage histogram

__global__ void k_init() {
    int t = blockIdx.x * blockDim.x + threadIdx.x;
    if (t < K) g_hist[t] = 0;
}

// en2[k] = sum_d e[d][k]^2  (sequential d, unfused square+add)
__global__ void k_en2(const float* __restrict__ e) {
    int k = blockIdx.x * blockDim.x + threadIdx.x;
    if (k >= K) return;
    float s = 0.f;
    for (int d = 0; d < D; ++d) {
        float v = e[d * K + k];
        s = __fadd_rn(s, __fmul_rn(v, v));
    }
    g_en2[k] = s;
}

// eT[k][d] = e[d][k]
__global__ void k_transpose(const float* __restrict__ e) {
    __shared__ float t[32][33];
    int kb = blockIdx.x * 32, db = blockIdx.y * 32;
    int tx = threadIdx.x, ty = threadIdx.y;  // 32 x 8
    #pragma unroll
    for (int i = 0; i < 32; i += 8)
        t[ty + i][tx] = e[(db + ty + i) * K + kb + tx];
    __syncthreads();
    #pragma unroll
    for (int i = 0; i < 32; i += 8)
        g_eT[(kb + ty + i) * D + db + tx] = t[tx][ty + i];
}

// zn2[n] = sum_d z[n][d]^2, strictly sequential d order, unfused square then add
__global__ void k_zn2(const float* __restrict__ z) {
    __shared__ float sz[32][257];
    int row0 = blockIdx.x * 32;
    int tid = threadIdx.x;  // 256
    #pragma unroll
    for (int i = 0; i < 32; i++) {
        int l = i * 256 + tid;
        int r = l >> 8, d = l & 255;
        sz[r][d] = z[(row0 + r) * D + d];
    }
    __syncthreads();
    if (tid < 32) {
        float s = 0.f;
        for (int d = 0; d < D; ++d) {
            float v = sz[tid][d];
            s = __fadd_rn(s, __fmul_rn(v, v));
        }
        g_zn2[row0 + tid] = s;
    }
}

// fused fp32 distance GEMM + per-row argmin (first-index tie-break)
#define BM 128
#define BN 128
#define BK 16
#define TM 8
#define TN 8
#define BMP 132

__global__ __launch_bounds__(256, 2)
void k_argmin(const float* __restrict__ z, const float* __restrict__ e) {
    __shared__ float s_zT[BK][BMP];
    __shared__ float s_e[BK][BN];
    __shared__ float s_en2[BN];
    __shared__ float m_v[BM][16];
    __shared__ int   m_i[BM][16];

    int tid = threadIdx.x;
    int tx = tid & 15, ty = tid >> 4;
    int row0 = blockIdx.x * BM;

    float bestv[TM];
    int   besti[TM];
    float my_zn2[TM];
    #pragma unroll
    for (int i = 0; i < TM; i++) {
        bestv[i] = INFINITY;
        besti[i] = 0;
        my_zn2[i] = g_zn2[row0 + ty * TM + i];
    }

    for (int kc = 0; kc < K; kc += BN) {
        __syncthreads();
        if (tid < BN) s_en2[tid] = g_en2[kc + tid];

        float acc[TM][TN];
        #pragma unroll
        for (int i = 0; i < TM; i++)
            #pragma unroll
            for (int j = 0; j < TN; j++) acc[i][j] = 0.f;

        for (int dk = 0; dk < D; dk += BK) {
            #pragma unroll
            for (int i = 0; i < 8; i++) {
                int l = i * 256 + tid;
                int r = l >> 4, d = l & 15;
                s_zT[d][r] = z[(row0 + r) * D + dk + d];
                int d2 = l >> 7, k2 = l & 127;
                s_e[d2][k2] = e[(dk + d2) * K + kc + k2];
            }
            __syncthreads();
            #pragma unroll
            for (int d = 0; d < BK; d++) {
                float a[TM], b[TN];
                float4 a0 = *(const float4*)&s_zT[d][ty * TM];
                float4 a1 = *(const float4*)&s_zT[d][ty * TM + 4];
                float4 b0 = *(const float4*)&s_e[d][tx * TN];
                float4 b1 = *(const float4*)&s_e[d][tx * TN + 4];
                a[0]=a0.x; a[1]=a0.y; a[2]=a0.z; a[3]=a0.w;
                a[4]=a1.x; a[5]=a1.y; a[6]=a1.z; a[7]=a1.w;
                b[0]=b0.x; b[1]=b0.y; b[2]=b0.z; b[3]=b0.w;
                b[4]=b1.x; b[5]=b1.y; b[6]=b1.z; b[7]=b1.w;
                #pragma unroll
                for (int i = 0; i < TM; i++)
                    #pragma unroll
                    for (int j = 0; j < TN; j++)
                        acc[i][j] = fmaf(a[i], b[j], acc[i][j]);
            }
            __syncthreads();
        }
        // epilogue: d = fl(zn2 + en2) - 2*t   (2*t exact; subtract rounds once, matching ref)
        #pragma unroll
        for (int i = 0; i < TM; i++) {
            #pragma unroll
            for (int j = 0; j < TN; j++) {
                float dist = __fsub_rn(__fadd_rn(my_zn2[i], s_en2[tx * TN + j]),
                                       2.0f * acc[i][j]);
                int code = kc + tx * TN + j;
                if (dist < bestv[i]) { bestv[i] = dist; besti[i] = code; }
            }
        }
    }

    __syncthreads();
    #pragma unroll
    for (int i = 0; i < TM; i++) {
        m_v[ty * TM + i][tx] = bestv[i];
        m_i[ty * TM + i][tx] = besti[i];
    }
    __syncthreads();
    if (tid < BM) {
        float bv = m_v[tid][0];
        int   bi = m_i[tid][0];
        #pragma unroll
        for (int t = 1; t < 16; t++) {
            float v = m_v[tid][t];
            int ii = m_i[tid][t];
            if (v < bv || (v == bv && ii < bi)) { bv = v; bi = ii; }
        }
        g_idx[row0 + tid] = bi;
    }
}

// gather quantized rows, straight-through output, loss partials, histogram
__global__ void k_gather(const float* __restrict__ z, float* __restrict__ out) {
    int warp = threadIdx.x >> 5, lane = threadIdx.x & 31;
    int row = blockIdx.x * 8 + warp;
    int k = g_idx[row];
    if (lane == 0) {
        atomicAdd(&g_hist[k], 1);
        out[QSIZE + row] = (float)k;
    }
    const float* er = &g_eT[k * D];
    const float* zr = z + row * D;
    float* qr = out + row * D;
    float ss = 0.f;
    #pragma unroll
    for (int d = lane; d < D; d += 32) {
        float q = er[d];
        float zv = zr[d];
        float diff = q - zv;
        ss = fmaf(diff, diff, ss);
        // quantized_st = fl(z + fl(q - z)) — replicate ref's rounding exactly
        qr[d] = __fadd_rn(zv, __fsub_rn(q, zv));
    }
    #pragma unroll
    for (int off = 16; off; off >>= 1)
        ss += __shfl_xor_sync(0xffffffffu, ss, off);
    __shared__ float wsum[8];
    if (lane == 0) wsum[warp] = ss;
    __syncthreads();
    if (threadIdx.x == 0) {
        float t = 0.f;
        for (int w = 0; w < 8; w++) t += wsum[w];
        g_part[blockIdx.x] = t;
    }
}

__global__ void k_final(float* __restrict__ out) {
    __shared__ double sd[256];
    int t = threadIdx.x;
    double s = 0.0;
    for (int i = t; i < 8192; i += 256) s += (double)g_part[i];
    sd[t] = s;
    __syncthreads();
    for (int off = 128; off; off >>= 1) {
        if (t < off) sd[t] += sd[t + off];
        __syncthreads();
    }
    if (t == 0) {
        float vq = (float)(sd[0] / (double)QSIZE);
        out[QSIZE + NROWS + 0] = vq;
        out[QSIZE + NROWS + 1] = 0.25f * vq;  // beta * same mean
        float ent = 0.f;
        for (int i = 0; i < K; i++) {
            float p = __fmul_rn((float)g_hist[i], 1.0f / 65536.0f);
            ent = __fadd_rn(ent, __fmul_rn(p, logf(__fadd_rn(p, 1e-10f))));
        }
        out[QSIZE + NROWS + 2] = expf(-ent);
    }
}

extern "C" void kernel_launch(void* const* d_in, const int* in_sizes, int n_in,
                              void* d_out, int out_size) {
    const float* z = (const float*)d_in[0];
    const float* e = (const float*)d_in[1];
    float* out = (float*)d_out;

    k_init<<<4, 256>>>();
    k_en2<<<4, 256>>>(e);
    k_transpose<<<dim3(K / 32, D / 32), dim3(32, 8)>>>(e);
    k_zn2<<<NROWS / 32, 256>>>(z);
    k_argmin<<<NROWS / BM, 256>>>(z, e);
    k_gather<<<NROWS / 8, 256>>>(z, out);
    k_final<<<1, 256>>>(out);
}